// round 6
// baseline (speedup 1.0000x reference)
#include <cuda_runtime.h>
#include <cstdint>

// Problem constants (fixed by the dataset: N_NODES=1M, D_IN=D_HID=64, 10 ratings)
#define MAX_E   1000000
#define NR      10
#define D       64
#define WSTRIDE 68                       // floats per k-row in smem (padded, 16B-aligned rows)
#define SMEM_BYTES (NR * D * WSTRIDE * 4)  // 174080 B

// ---------------- static device scratch (no runtime allocation) ----------------
__device__ int   g_bin_count[NR];
__device__ int   g_is64;                   // 1 if index arrays are int64, else int32
__device__ int   g_node_buf[NR * MAX_E];   // per-bucket gathered node ids   (40 MB)
__device__ float g_invc_buf[NR * MAX_E];   // per-bucket gathered inv_c      (40 MB)

// ---------------- kernel 1: reset counters + detect index dtype ----------------
// Ratings are uniform in [0,10). Viewed as int32 words, an int64 array has the
// high word (==0) at every odd position; an int32 array has random ratings
// there. 32 consecutive odd-position zeros => int64 (false-positive ~1e-32,
// and deterministic per input, so graph-replay safe).
__global__ void init_kernel(const int* __restrict__ rating_as_i32, int E) {
    int t = threadIdx.x;
    if (t < NR) g_bin_count[t] = 0;
    int probe = (t < 32 && (2 * t + 1) < E) ? rating_as_i32[2 * t + 1] : 0;
    unsigned all_zero = __ballot_sync(0xFFFFFFFFu, probe == 0);
    if (t == 0) g_is64 = (all_zero == 0xFFFFFFFFu) ? 1 : 0;
}

// ---------------- kernel 2: bucket rows by rating ----------------
// Block-local histogram -> one global atomicAdd per (block, bin) to reserve a
// range -> scatter (node, inv_c) into the bucket regions. Order within a
// bucket is irrelevant (node ids are unique).
__global__ void bucket_scatter_kernel(const void*  __restrict__ edge_node,
                                      const void*  __restrict__ edge_rating,
                                      const float* __restrict__ inv_c,
                                      int E) {
    __shared__ int s_cnt[NR];
    __shared__ int s_base[NR];
    __shared__ int s_off[NR];
    int t = threadIdx.x;
    if (t < NR) { s_cnt[t] = 0; s_off[t] = 0; }
    __syncthreads();

    const int is64 = g_is64;
    const int*       rat32 = (const int*)edge_rating;
    const long long* rat64 = (const long long*)edge_rating;
    const int*       nod32 = (const int*)edge_node;
    const long long* nod64 = (const long long*)edge_node;

    int chunk = (E + gridDim.x - 1) / gridDim.x;
    int start = blockIdx.x * chunk;
    int end   = min(start + chunk, E);

    for (int e = start + t; e < end; e += blockDim.x) {
        int r = is64 ? (int)rat64[e] : rat32[e];
        r = min(max(r, 0), NR - 1);
        atomicAdd(&s_cnt[r], 1);
    }
    __syncthreads();
    if (t < NR) s_base[t] = atomicAdd(&g_bin_count[t], s_cnt[t]);
    __syncthreads();
    for (int e = start + t; e < end; e += blockDim.x) {
        int r = is64 ? (int)rat64[e] : rat32[e];
        r = min(max(r, 0), NR - 1);
        int pos = s_base[r] + atomicAdd(&s_off[r], 1);
        pos = min(pos, MAX_E - 1);
        g_node_buf[r * MAX_E + pos] = is64 ? (int)nod64[e] : nod32[e];
        g_invc_buf[r * MAX_E + pos] = inv_c[e];
    }
}

// ---------------- kernel 3: rating-grouped matvec ----------------
// 148 persistent blocks x 512 threads. All 10 weight matrices live transposed
// in SMEM: s_wt[(r*64 + k)*WSTRIDE + j] = W[r][j][k]. A warp processes 32 rows
// of ONE rating: weight reads are warp-uniform broadcasts (ld.shared.v2.u64),
// x lives in 64 registers per lane, accumulation uses packed fma.rn.f32x2.
extern __shared__ float s_wt[];

#define FMA2(acc, w2, x2) \
    asm("fma.rn.f32x2 %0, %1, %2, %0;" : "+l"(acc) : "l"(w2), "l"(x2))

__global__ __launch_bounds__(512, 1)
void rating_matvec_kernel(const float* __restrict__ embed,
                          const float* __restrict__ weights,
                          float*       __restrict__ out,
                          int n_nodes) {
    // Transposed cooperative weight load (global reads coalesced over the
    // contiguous k index; smem writes j-strided but one-time cost).
    for (int idx = threadIdx.x; idx < NR * D * D; idx += blockDim.x) {
        int r = idx >> 12;
        int j = (idx >> 6) & 63;
        int k = idx & 63;
        s_wt[(r * D + k) * WSTRIDE + j] = weights[idx];
    }
    __syncthreads();

    int lane = threadIdx.x & 31;
    int gw   = blockIdx.x * (blockDim.x >> 5) + (threadIdx.x >> 5);
    int totW = gridDim.x * (blockDim.x >> 5);

    for (int r = 0; r < NR; ++r) {
        int cnt    = min(g_bin_count[r], MAX_E);
        int nTasks = (cnt + 31) >> 5;
        const float* wr = s_wt + r * D * WSTRIDE;

        for (int task = gw; task < nTasks; task += totW) {
            int  s    = (task << 5) + lane;
            bool act  = s < cnt;
            int  node = act ? g_node_buf[r * MAX_E + s] : 0;
            // Clamp: never fault — a wrong answer is diagnosable, a crash isn't.
            node = min(max(node, 0), n_nodes - 1);
            float invc = act ? g_invc_buf[r * MAX_E + s] : 0.f;

            // Load this lane's row into registers (16x LDG.128, sector-exact).
            float x[D];
            const float4* xp = (const float4*)(embed + (size_t)node * D);
            #pragma unroll
            for (int i = 0; i < 16; ++i) {
                float4 v = xp[i];
                x[4*i+0] = v.x; x[4*i+1] = v.y; x[4*i+2] = v.z; x[4*i+3] = v.w;
            }

            float4* op = (float4*)(out + (size_t)node * D);

            #pragma unroll
            for (int jc = 0; jc < 4; ++jc) {          // 16 outputs per chunk
                unsigned long long acc[8];
                #pragma unroll
                for (int p = 0; p < 8; ++p) acc[p] = 0ull;

                #pragma unroll
                for (int k = 0; k < D; ++k) {
                    unsigned long long xk2;
                    asm("mov.b64 %0, {%1, %1};" : "=l"(xk2) : "f"(x[k]));
                    const ulonglong2* wp =
                        (const ulonglong2*)(wr + k * WSTRIDE + jc * 16);
                    ulonglong2 w0 = wp[0];   // j: +0..3   (two f32x2 pairs)
                    ulonglong2 w1 = wp[1];   // j: +4..7
                    ulonglong2 w2 = wp[2];   // j: +8..11
                    ulonglong2 w3 = wp[3];   // j: +12..15
                    FMA2(acc[0], w0.x, xk2);
                    FMA2(acc[1], w0.y, xk2);
                    FMA2(acc[2], w1.x, xk2);
                    FMA2(acc[3], w1.y, xk2);
                    FMA2(acc[4], w2.x, xk2);
                    FMA2(acc[5], w2.y, xk2);
                    FMA2(acc[6], w3.x, xk2);
                    FMA2(acc[7], w3.y, xk2);
                }

                if (act) {
                    #pragma unroll
                    for (int p = 0; p < 4; ++p) {
                        float a, b, c, d;
                        asm("mov.b64 {%0, %1}, %2;" : "=f"(a), "=f"(b) : "l"(acc[2*p]));
                        asm("mov.b64 {%0, %1}, %2;" : "=f"(c), "=f"(d) : "l"(acc[2*p+1]));
                        float4 o;
                        o.x = a * invc; o.y = b * invc; o.z = c * invc; o.w = d * invc;
                        op[jc * 4 + p] = o;
                    }
                }
            }
        }
    }
}

// ---------------- launch ----------------
extern "C" void kernel_launch(void* const* d_in, const int* in_sizes, int n_in,
                              void* d_out, int out_size) {
    const float* embed       = (const float*)d_in[0];
    const float* weights     = (const float*)d_in[1];
    const float* inv_c       = (const float*)d_in[2];
    const void*  edge_node   = d_in[3];
    const void*  edge_rating = d_in[4];
    int E       = in_sizes[3];
    int n_nodes = out_size / D;

    // Needed for >48KB dynamic SMEM; immediate API, safe under graph capture.
    (void)cudaFuncSetAttribute(rating_matvec_kernel,
                               cudaFuncAttributeMaxDynamicSharedMemorySize,
                               SMEM_BYTES);

    init_kernel<<<1, 32>>>((const int*)edge_rating, E);
    bucket_scatter_kernel<<<512, 256>>>(edge_node, edge_rating, inv_c, E);
    rating_matvec_kernel<<<148, 512, SMEM_BYTES>>>(embed, weights,
                                                   (float*)d_out, n_nodes);
}

// round 9
// speedup vs baseline: 1.5051x; 1.5051x over previous
#include <cuda_runtime.h>
#include <cstdint>

// Problem constants (fixed by the dataset: N_NODES=1M, D_IN=D_HID=64, 10 ratings)
#define MAX_E   1000000
#define NR      10
#define D       64
#define WSTRIDE 68                        // floats per k-row in smem (pad kills conflicts)
#define W_SMEM_BYTES (D * WSTRIDE * 4)    // 17408 B (one rating's matrix)
#define BPR     148                       // blocks per rating
#define TPB     256                       // threads per block (8 warps)

// ---------------- static device scratch (no runtime allocation) ----------------
__device__ int   g_bin_count[NR];
__device__ int   g_is64;                   // 1 if index arrays are int64, else int32
__device__ int   g_node_buf[NR * MAX_E];   // per-bucket gathered node ids   (40 MB)
__device__ float g_invc_buf[NR * MAX_E];   // per-bucket gathered inv_c      (40 MB)

// ---------------- kernel 1: reset counters + detect index dtype ----------------
// Ratings are uniform in [0,10). Viewed as int32 words, an int64 array has the
// zero high word at every odd position; an int32 array has random ratings
// there. 32 consecutive odd-position zeros => int64 (false-positive ~1e-32,
// deterministic per input => graph-replay safe).
__global__ void init_kernel(const int* __restrict__ rating_as_i32, int E) {
    int t = threadIdx.x;
    if (t < NR) g_bin_count[t] = 0;
    int probe = (t < 32 && (2 * t + 1) < E) ? rating_as_i32[2 * t + 1] : 0;
    unsigned all_zero = __ballot_sync(0xFFFFFFFFu, probe == 0);
    if (t == 0) g_is64 = (all_zero == 0xFFFFFFFFu) ? 1 : 0;
}

// ---------------- kernel 2: bucket rows by rating ----------------
// Block-local histogram -> one global atomicAdd per (block, bin) to reserve a
// range -> scatter (node, inv_c) into the bucket regions. Order within a
// bucket is irrelevant (node ids are unique).
__global__ void bucket_scatter_kernel(const void*  __restrict__ edge_node,
                                      const void*  __restrict__ edge_rating,
                                      const float* __restrict__ inv_c,
                                      int E) {
    __shared__ int s_cnt[NR];
    __shared__ int s_base[NR];
    __shared__ int s_off[NR];
    int t = threadIdx.x;
    if (t < NR) { s_cnt[t] = 0; s_off[t] = 0; }
    __syncthreads();

    const int is64 = g_is64;
    const int*       rat32 = (const int*)edge_rating;
    const long long* rat64 = (const long long*)edge_rating;
    const int*       nod32 = (const int*)edge_node;
    const long long* nod64 = (const long long*)edge_node;

    int chunk = (E + gridDim.x - 1) / gridDim.x;
    int start = blockIdx.x * chunk;
    int end   = min(start + chunk, E);

    #pragma unroll 4
    for (int e = start + t; e < end; e += blockDim.x) {
        int r = is64 ? (int)rat64[e] : rat32[e];
        r = min(max(r, 0), NR - 1);
        atomicAdd(&s_cnt[r], 1);
    }
    __syncthreads();
    if (t < NR) s_base[t] = atomicAdd(&g_bin_count[t], s_cnt[t]);
    __syncthreads();
    #pragma unroll 4
    for (int e = start + t; e < end; e += blockDim.x) {
        int r = is64 ? (int)rat64[e] : rat32[e];
        r = min(max(r, 0), NR - 1);
        int pos = s_base[r] + atomicAdd(&s_off[r], 1);
        pos = min(pos, MAX_E - 1);
        g_node_buf[r * MAX_E + pos] = is64 ? (int)nod64[e] : nod32[e];
        g_invc_buf[r * MAX_E + pos] = inv_c[e];
    }
}

// ---------------- kernel 3: rating-grouped matvec (one rating per block) ----------------
// Grid = NR*BPR blocks of 256 threads; block handles ONE rating, so SMEM holds
// a single transposed 64x64 matrix (17 KB) -> >=2 CTAs/SM. A warp processes 32
// rows: weight reads are warp-uniform LDS.128 broadcasts, x lives in 64 regs
// per lane, accumulation in packed fma.rn.f32x2, 8 outputs per pass (acc kept
// tiny to hold peak regs ~95 < the 128-reg cap => no local-memory spill).
#define FMA2(acc, w2, x2) \
    asm("fma.rn.f32x2 %0, %1, %2, %0;" : "+l"(acc) : "l"(w2), "l"(x2))

__global__ __launch_bounds__(TPB, 2)
void rating_matvec_kernel(const float* __restrict__ embed,
                          const float* __restrict__ weights,
                          float*       __restrict__ out,
                          int n_nodes) {
    __shared__ float s_wt[D * WSTRIDE];   // s_wt[k*WSTRIDE + j] = W[r][j][k]

    int r = blockIdx.x / BPR;             // this block's rating
    int b = blockIdx.x % BPR;             // index within the rating's block group

    // Cooperative transposed load of W[r] (reads coalesced over contiguous k).
    const float* wsrc = weights + r * D * D;
    for (int idx = threadIdx.x; idx < D * D; idx += TPB) {
        int j = idx >> 6;
        int k = idx & 63;
        s_wt[k * WSTRIDE + j] = wsrc[idx];
    }
    __syncthreads();

    int lane = threadIdx.x & 31;
    int gw   = b * (TPB >> 5) + (threadIdx.x >> 5);   // warp id within rating group
    int totW = BPR * (TPB >> 5);

    int cnt    = min(g_bin_count[r], MAX_E);
    int nTasks = (cnt + 31) >> 5;

    for (int task = gw; task < nTasks; task += totW) {
        int  s    = (task << 5) + lane;
        bool act  = s < cnt;
        int  node = act ? g_node_buf[r * MAX_E + s] : 0;
        node = min(max(node, 0), n_nodes - 1);        // never fault
        float invc = act ? g_invc_buf[r * MAX_E + s] : 0.f;

        // Load this lane's row into registers (16x LDG.128, sector-exact).
        float x[D];
        const float4* xp = (const float4*)(embed + (size_t)node * D);
        #pragma unroll
        for (int i = 0; i < 16; ++i) {
            float4 v = xp[i];
            x[4*i+0] = v.x; x[4*i+1] = v.y; x[4*i+2] = v.z; x[4*i+3] = v.w;
        }

        float4* op = (float4*)(out + (size_t)node * D);

        #pragma unroll
        for (int jc = 0; jc < 8; ++jc) {              // 8 outputs per pass
            unsigned long long acc[4];
            #pragma unroll
            for (int p = 0; p < 4; ++p) acc[p] = 0ull;

            #pragma unroll
            for (int k = 0; k < D; ++k) {
                unsigned long long xk2;
                asm("mov.b64 %0, {%1, %1};" : "=l"(xk2) : "f"(x[k]));
                const ulonglong2* wp =
                    (const ulonglong2*)(s_wt + k * WSTRIDE + jc * 8);
                ulonglong2 w0 = wp[0];   // outputs jc*8+0..3 (two f32x2 pairs)
                ulonglong2 w1 = wp[1];   // outputs jc*8+4..7
                FMA2(acc[0], w0.x, xk2);
                FMA2(acc[1], w0.y, xk2);
                FMA2(acc[2], w1.x, xk2);
                FMA2(acc[3], w1.y, xk2);
            }

            if (act) {
                #pragma unroll
                for (int p = 0; p < 2; ++p) {
                    float a0, a1, a2, a3;
                    asm("mov.b64 {%0, %1}, %2;" : "=f"(a0), "=f"(a1) : "l"(acc[2*p]));
                    asm("mov.b64 {%0, %1}, %2;" : "=f"(a2), "=f"(a3) : "l"(acc[2*p+1]));
                    float4 o;
                    o.x = a0 * invc; o.y = a1 * invc;
                    o.z = a2 * invc; o.w = a3 * invc;
                    op[jc * 2 + p] = o;
                }
            }
        }
    }
}

// ---------------- launch ----------------
extern "C" void kernel_launch(void* const* d_in, const int* in_sizes, int n_in,
                              void* d_out, int out_size) {
    const float* embed       = (const float*)d_in[0];
    const float* weights     = (const float*)d_in[1];
    const float* inv_c       = (const float*)d_in[2];
    const void*  edge_node   = d_in[3];
    const void*  edge_rating = d_in[4];
    int E       = in_sizes[3];
    int n_nodes = out_size / D;

    init_kernel<<<1, 32>>>((const int*)edge_rating, E);
    bucket_scatter_kernel<<<512, 256>>>(edge_node, edge_rating, inv_c, E);
    rating_matvec_kernel<<<NR * BPR, TPB>>>(embed, weights, (float*)d_out, n_nodes);
}

// round 10
// speedup vs baseline: 1.5058x; 1.0005x over previous
#include <cuda_runtime.h>
#include <cstdint>

// Problem constants (fixed by the dataset: N_NODES=1M, D_IN=D_HID=64, 10 ratings)
#define MAX_E   1000000
#define NR      10
#define D       64
#define WSTRIDE 68                        // floats per k-row in smem (pad kills conflicts)
#define W_SMEM_BYTES (D * WSTRIDE * 4)    // 17408 B (one rating's matrix)
#define BPR     148                       // blocks per rating
#define TPB     256                       // threads per block (8 warps)

// ---------------- static device scratch (no runtime allocation) ----------------
__device__ int   g_bin_count[NR];
__device__ int   g_is64;                   // 1 if index arrays are int64, else int32
__device__ int   g_node_buf[NR * MAX_E];   // per-bucket gathered node ids   (40 MB)
__device__ float g_invc_buf[NR * MAX_E];   // per-bucket gathered inv_c      (40 MB)

// ---------------- kernel 1: reset counters + detect index dtype ----------------
// Ratings are uniform in [0,10). Viewed as int32 words, an int64 array has the
// zero high word at every odd position; an int32 array has random ratings
// there. 32 consecutive odd-position zeros => int64 (false-positive ~1e-32,
// deterministic per input => graph-replay safe).
__global__ void init_kernel(const int* __restrict__ rating_as_i32, int E) {
    int t = threadIdx.x;
    if (t < NR) g_bin_count[t] = 0;
    int probe = (t < 32 && (2 * t + 1) < E) ? rating_as_i32[2 * t + 1] : 0;
    unsigned all_zero = __ballot_sync(0xFFFFFFFFu, probe == 0);
    if (t == 0) g_is64 = (all_zero == 0xFFFFFFFFu) ? 1 : 0;
}

// ---------------- kernel 2: bucket rows by rating ----------------
// Block-local histogram -> one global atomicAdd per (block, bin) to reserve a
// range -> scatter (node, inv_c) into the bucket regions. Order within a
// bucket is irrelevant (node ids are unique).
__global__ void bucket_scatter_kernel(const void*  __restrict__ edge_node,
                                      const void*  __restrict__ edge_rating,
                                      const float* __restrict__ inv_c,
                                      int E) {
    __shared__ int s_cnt[NR];
    __shared__ int s_base[NR];
    __shared__ int s_off[NR];
    int t = threadIdx.x;
    if (t < NR) { s_cnt[t] = 0; s_off[t] = 0; }
    __syncthreads();

    const int is64 = g_is64;
    const int*       rat32 = (const int*)edge_rating;
    const long long* rat64 = (const long long*)edge_rating;
    const int*       nod32 = (const int*)edge_node;
    const long long* nod64 = (const long long*)edge_node;

    int chunk = (E + gridDim.x - 1) / gridDim.x;
    int start = blockIdx.x * chunk;
    int end   = min(start + chunk, E);

    #pragma unroll 4
    for (int e = start + t; e < end; e += blockDim.x) {
        int r = is64 ? (int)rat64[e] : rat32[e];
        r = min(max(r, 0), NR - 1);
        atomicAdd(&s_cnt[r], 1);
    }
    __syncthreads();
    if (t < NR) s_base[t] = atomicAdd(&g_bin_count[t], s_cnt[t]);
    __syncthreads();
    #pragma unroll 4
    for (int e = start + t; e < end; e += blockDim.x) {
        int r = is64 ? (int)rat64[e] : rat32[e];
        r = min(max(r, 0), NR - 1);
        int pos = s_base[r] + atomicAdd(&s_off[r], 1);
        pos = min(pos, MAX_E - 1);
        g_node_buf[r * MAX_E + pos] = is64 ? (int)nod64[e] : nod32[e];
        g_invc_buf[r * MAX_E + pos] = inv_c[e];
    }
}

// ---------------- kernel 3: rating-grouped matvec (one rating per block) ----------------
// Grid = NR*BPR blocks of 256 threads; block handles ONE rating, so SMEM holds
// a single transposed 64x64 matrix (17 KB) -> >=2 CTAs/SM. A warp processes 32
// rows: weight reads are warp-uniform LDS.128 broadcasts, x lives in 64 regs
// per lane, accumulation in packed fma.rn.f32x2, 8 outputs per pass (acc kept
// tiny to hold peak regs ~95 < the 128-reg cap => no local-memory spill).
#define FMA2(acc, w2, x2) \
    asm("fma.rn.f32x2 %0, %1, %2, %0;" : "+l"(acc) : "l"(w2), "l"(x2))

__global__ __launch_bounds__(TPB, 2)
void rating_matvec_kernel(const float* __restrict__ embed,
                          const float* __restrict__ weights,
                          float*       __restrict__ out,
                          int n_nodes) {
    __shared__ float s_wt[D * WSTRIDE];   // s_wt[k*WSTRIDE + j] = W[r][j][k]

    int r = blockIdx.x / BPR;             // this block's rating
    int b = blockIdx.x % BPR;             // index within the rating's block group

    // Cooperative transposed load of W[r] (reads coalesced over contiguous k).
    const float* wsrc = weights + r * D * D;
    for (int idx = threadIdx.x; idx < D * D; idx += TPB) {
        int j = idx >> 6;
        int k = idx & 63;
        s_wt[k * WSTRIDE + j] = wsrc[idx];
    }
    __syncthreads();

    int lane = threadIdx.x & 31;
    int gw   = b * (TPB >> 5) + (threadIdx.x >> 5);   // warp id within rating group
    int totW = BPR * (TPB >> 5);

    int cnt    = min(g_bin_count[r], MAX_E);
    int nTasks = (cnt + 31) >> 5;

    for (int task = gw; task < nTasks; task += totW) {
        int  s    = (task << 5) + lane;
        bool act  = s < cnt;
        int  node = act ? g_node_buf[r * MAX_E + s] : 0;
        node = min(max(node, 0), n_nodes - 1);        // never fault
        float invc = act ? g_invc_buf[r * MAX_E + s] : 0.f;

        // Load this lane's row into registers (16x LDG.128, sector-exact).
        float x[D];
        const float4* xp = (const float4*)(embed + (size_t)node * D);
        #pragma unroll
        for (int i = 0; i < 16; ++i) {
            float4 v = xp[i];
            x[4*i+0] = v.x; x[4*i+1] = v.y; x[4*i+2] = v.z; x[4*i+3] = v.w;
        }

        float4* op = (float4*)(out + (size_t)node * D);

        #pragma unroll
        for (int jc = 0; jc < 8; ++jc) {              // 8 outputs per pass
            unsigned long long acc[4];
            #pragma unroll
            for (int p = 0; p < 4; ++p) acc[p] = 0ull;

            #pragma unroll
            for (int k = 0; k < D; ++k) {
                unsigned long long xk2;
                asm("mov.b64 %0, {%1, %1};" : "=l"(xk2) : "f"(x[k]));
                const ulonglong2* wp =
                    (const ulonglong2*)(s_wt + k * WSTRIDE + jc * 8);
                ulonglong2 w0 = wp[0];   // outputs jc*8+0..3 (two f32x2 pairs)
                ulonglong2 w1 = wp[1];   // outputs jc*8+4..7
                FMA2(acc[0], w0.x, xk2);
                FMA2(acc[1], w0.y, xk2);
                FMA2(acc[2], w1.x, xk2);
                FMA2(acc[3], w1.y, xk2);
            }

            if (act) {
                #pragma unroll
                for (int p = 0; p < 2; ++p) {
                    float a0, a1, a2, a3;
                    asm("mov.b64 {%0, %1}, %2;" : "=f"(a0), "=f"(a1) : "l"(acc[2*p]));
                    asm("mov.b64 {%0, %1}, %2;" : "=f"(a2), "=f"(a3) : "l"(acc[2*p+1]));
                    float4 o;
                    o.x = a0 * invc; o.y = a1 * invc;
                    o.z = a2 * invc; o.w = a3 * invc;
                    op[jc * 2 + p] = o;
                }
            }
        }
    }
}

// ---------------- launch ----------------
extern "C" void kernel_launch(void* const* d_in, const int* in_sizes, int n_in,
                              void* d_out, int out_size) {
    const float* embed       = (const float*)d_in[0];
    const float* weights     = (const float*)d_in[1];
    const float* inv_c       = (const float*)d_in[2];
    const void*  edge_node   = d_in[3];
    const void*  edge_rating = d_in[4];
    int E       = in_sizes[3];
    int n_nodes = out_size / D;

    init_kernel<<<1, 32>>>((const int*)edge_rating, E);
    bucket_scatter_kernel<<<512, 256>>>(edge_node, edge_rating, inv_c, E);
    rating_matvec_kernel<<<NR * BPR, TPB>>>(embed, weights, (float*)d_out, n_nodes);
}

// round 11
// speedup vs baseline: 2.7805x; 1.8465x over previous
#include <cuda_runtime.h>
#include <cstdint>

// Problem constants (fixed by the dataset: N_NODES=1M, D_IN=D_HID=64, 10 ratings)
#define MAX_E   1000000
#define NR      10
#define D       64
#define BPR     148                       // blocks per rating
#define TPB     256                       // threads per block (8 warps)
#define W4_BYTES   16384                  // 32 k2 x 32 jpair x 16B
#define XT_BYTES   (8 * 32 * D * 4)       // 8 warps x 32 rows x 64 f32 = 64 KB
#define SMEM_BYTES (W4_BYTES + XT_BYTES)  // 80 KB dynamic

// ---------------- static device scratch (no runtime allocation) ----------------
__device__ int   g_bin_count[NR];
__device__ int   g_is64;                   // 1 if index arrays are int64, else int32
__device__ int   g_node_buf[NR * MAX_E];   // per-bucket gathered node ids   (40 MB)
__device__ float g_invc_buf[NR * MAX_E];   // per-bucket gathered inv_c      (40 MB)

// ---------------- kernel 1: reset counters + detect index dtype ----------------
__global__ void init_kernel(const int* __restrict__ rating_as_i32, int E) {
    int t = threadIdx.x;
    if (t < NR) g_bin_count[t] = 0;
    int probe = (t < 32 && (2 * t + 1) < E) ? rating_as_i32[2 * t + 1] : 0;
    unsigned all_zero = __ballot_sync(0xFFFFFFFFu, probe == 0);
    if (t == 0) g_is64 = (all_zero == 0xFFFFFFFFu) ? 1 : 0;
}

// ---------------- kernel 2: bucket rows by rating ----------------
__global__ void bucket_scatter_kernel(const void*  __restrict__ edge_node,
                                      const void*  __restrict__ edge_rating,
                                      const float* __restrict__ inv_c,
                                      int E) {
    __shared__ int s_cnt[NR];
    __shared__ int s_base[NR];
    __shared__ int s_off[NR];
    int t = threadIdx.x;
    if (t < NR) { s_cnt[t] = 0; s_off[t] = 0; }
    __syncthreads();

    const int is64 = g_is64;
    const int*       rat32 = (const int*)edge_rating;
    const long long* rat64 = (const long long*)edge_rating;
    const int*       nod32 = (const int*)edge_node;
    const long long* nod64 = (const long long*)edge_node;

    int chunk = (E + gridDim.x - 1) / gridDim.x;
    int start = blockIdx.x * chunk;
    int end   = min(start + chunk, E);

    #pragma unroll 4
    for (int e = start + t; e < end; e += blockDim.x) {
        int r = is64 ? (int)rat64[e] : rat32[e];
        r = min(max(r, 0), NR - 1);
        atomicAdd(&s_cnt[r], 1);
    }
    __syncthreads();
    if (t < NR) s_base[t] = atomicAdd(&g_bin_count[t], s_cnt[t]);
    __syncthreads();
    #pragma unroll 4
    for (int e = start + t; e < end; e += blockDim.x) {
        int r = is64 ? (int)rat64[e] : rat32[e];
        r = min(max(r, 0), NR - 1);
        int pos = s_base[r] + atomicAdd(&s_off[r], 1);
        pos = min(pos, MAX_E - 1);
        g_node_buf[r * MAX_E + pos] = is64 ? (int)nod64[e] : nod32[e];
        g_invc_buf[r * MAX_E + pos] = inv_c[e];
    }
}

// ---------------- kernel 3: rating-grouped matvec, output-per-lane ----------------
// One rating per block (grid = NR*BPR). Warp task = 32 rows.
//   * Lane owns output pair j = (2*lane, 2*lane+1).
//   * Gather: cooperative LDG.128 (2 full rows / instr -> 4 lines, not 32) into a
//     per-warp SMEM x-tile; all compute reads of x are warp-uniform broadcasts.
//   * Weights pre-paired in SMEM as ulonglong2 { (W[2l][2k2],W[2l][2k2+1]),
//     (W[2l+1][2k2],W[2l+1][2k2+1]) }; cooperative conflict-free LDS.128 into regs.
//   * acc = f32x2 over (k even, k odd); epilogue adds halves, scales, STG.64/row.
#define FMA2(acc, w2, x2) \
    asm("fma.rn.f32x2 %0, %1, %2, %0;" : "+l"(acc) : "l"(w2), "l"(x2))

__global__ __launch_bounds__(TPB, 2)
void rating_matvec_kernel(const float* __restrict__ embed,
                          const float* __restrict__ weights,
                          float*       __restrict__ out,
                          int n_nodes) {
    extern __shared__ char s_mem[];
    ulonglong2* s_w4 = (ulonglong2*)s_mem;                  // [k2*32 + jpair]

    int r = blockIdx.x / BPR;
    int b = blockIdx.x % BPR;

    // One-time weight prep: pair along k for each output j.
    const float* wsrc = weights + r * D * D;
    for (int idx = threadIdx.x; idx < 1024; idx += TPB) {
        int k2 = idx >> 5;
        int j2 = idx & 31;
        ulonglong2 v;
        v.x = *(const unsigned long long*)(wsrc + (2 * j2)     * D + 2 * k2);
        v.y = *(const unsigned long long*)(wsrc + (2 * j2 + 1) * D + 2 * k2);
        s_w4[idx] = v;
    }
    __syncthreads();

    int lane = threadIdx.x & 31;
    int warp = threadIdx.x >> 5;
    float*  xt  = (float*)(s_mem + W4_BYTES) + warp * (32 * D);
    float4* xt4 = (float4*)xt;

    int gw   = b * (TPB >> 5) + warp;
    int totW = BPR * (TPB >> 5);
    int cnt    = min(g_bin_count[r], MAX_E);
    int nTasks = (cnt + 31) >> 5;

    for (int task = gw; task < nTasks; task += totW) {
        int  sbase = task << 5;
        int  s     = sbase + lane;
        bool act   = s < cnt;
        int  node  = act ? g_node_buf[r * MAX_E + s] : 0;
        node = min(max(node, 0), n_nodes - 1);              // never fault
        float invc = act ? g_invc_buf[r * MAX_E + s] : 0.f;

        // Cooperative gather: instr i moves rows 2i and 2i+1 completely.
        int chunk = lane & 15;
        int half  = lane >> 4;
        #pragma unroll
        for (int i = 0; i < 16; ++i) {
            int row = 2 * i + half;
            int nd  = __shfl_sync(0xFFFFFFFFu, node, row);
            float4 v = ((const float4*)(embed + (size_t)nd * D))[chunk];
            xt4[row * 16 + chunk] = v;
        }
        __syncwarp();

        #pragma unroll
        for (int rb = 0; rb < 2; ++rb) {
            unsigned long long a0[16], a1[16];
            #pragma unroll
            for (int q = 0; q < 16; ++q) { a0[q] = 0ull; a1[q] = 0ull; }

            for (int kg = 0; kg < 4; ++kg) {                // 16 k per group
                ulonglong2 w4[8];                           // k2 = kg*8 .. +7
                #pragma unroll
                for (int t = 0; t < 8; ++t)
                    w4[t] = s_w4[(kg * 8 + t) * 32 + lane]; // conflict-free

                const float* xbase = xt + rb * 16 * D + kg * 16;
                #pragma unroll
                for (int q = 0; q < 16; ++q) {
                    const ulonglong2* xp =
                        (const ulonglong2*)(xbase + q * D);  // warp-uniform addr
                    #pragma unroll
                    for (int t = 0; t < 4; ++t) {
                        ulonglong2 pp = xp[t];               // x pairs 2t, 2t+1
                        FMA2(a0[q], w4[2 * t].x,     pp.x);
                        FMA2(a1[q], w4[2 * t].y,     pp.x);
                        FMA2(a0[q], w4[2 * t + 1].x, pp.y);
                        FMA2(a1[q], w4[2 * t + 1].y, pp.y);
                    }
                }
            }

            // Epilogue: reduce even/odd halves, scale, cooperative STG.64 per row.
            #pragma unroll
            for (int q = 0; q < 16; ++q) {
                int row = rb * 16 + q;
                float e0, o0, e1, o1;
                asm("mov.b64 {%0, %1}, %2;" : "=f"(e0), "=f"(o0) : "l"(a0[q]));
                asm("mov.b64 {%0, %1}, %2;" : "=f"(e1), "=f"(o1) : "l"(a1[q]));
                float ic = __shfl_sync(0xFFFFFFFFu, invc, row);
                int   nd = __shfl_sync(0xFFFFFFFFu, node, row);
                if (sbase + row < cnt) {
                    float2 o;
                    o.x = (e0 + o0) * ic;
                    o.y = (e1 + o1) * ic;
                    ((float2*)(out + (size_t)nd * D))[lane] = o;
                }
            }
        }
    }
}

// ---------------- launch ----------------
extern "C" void kernel_launch(void* const* d_in, const int* in_sizes, int n_in,
                              void* d_out, int out_size) {
    const float* embed       = (const float*)d_in[0];
    const float* weights     = (const float*)d_in[1];
    const float* inv_c       = (const float*)d_in[2];
    const void*  edge_node   = d_in[3];
    const void*  edge_rating = d_in[4];
    int E       = in_sizes[3];
    int n_nodes = out_size / D;

    // >48KB dynamic SMEM; immediate API, safe under graph capture.
    (void)cudaFuncSetAttribute(rating_matvec_kernel,
                               cudaFuncAttributeMaxDynamicSharedMemorySize,
                               SMEM_BYTES);

    init_kernel<<<1, 32>>>((const int*)edge_rating, E);
    bucket_scatter_kernel<<<512, 256>>>(edge_node, edge_rating, inv_c, E);
    rating_matvec_kernel<<<NR * BPR, TPB, SMEM_BYTES>>>(embed, weights,
                                                        (float*)d_out, n_nodes);
}